// round 1
// baseline (speedup 1.0000x reference)
#include <cuda_runtime.h>
#include <cstdint>

#define N_NODES 100000
#define N_EDGES 640000
#define D       128
#define K2      256            // combined K: [mean_agg | relu(x)]
#define BN_EPS  1e-5f

#define TM        64           // node rows per tile
#define AS_STRIDE 260          // padded shared stride (floats) to dodge bank conflicts

// ---------------- scratch (static __device__: no allocations allowed) ----------------
__device__ float g_agg[N_NODES * D];   // scatter-add accumulator
__device__ float g_cnt[N_NODES];       // in-degree
__device__ float g_sum[D];             // BN partial sums
__device__ float g_sumsq[D];           // BN partial sums of squares

// ---------------- kernel 1: zero scratch ----------------
__global__ void zero_kernel() {
    const int stride = gridDim.x * blockDim.x;
    int i = blockIdx.x * blockDim.x + threadIdx.x;
    float4 z = make_float4(0.f, 0.f, 0.f, 0.f);
    float4* a4 = reinterpret_cast<float4*>(g_agg);
    const int nAgg4 = (N_NODES * D) / 4;          // 3.2M
    for (int idx = i; idx < nAgg4; idx += stride) a4[idx] = z;
    float4* c4 = reinterpret_cast<float4*>(g_cnt);
    const int nCnt4 = N_NODES / 4;                // 25k
    for (int idx = i; idx < nCnt4; idx += stride) c4[idx] = z;
    if (i < D) { g_sum[i] = 0.f; g_sumsq[i] = 0.f; }
}

// ---------------- kernel 2: edge scatter (one warp per edge) ----------------
__global__ void scatter_kernel(const float4* __restrict__ x4,
                               const int* __restrict__ ei) {
    int w    = (blockIdx.x * blockDim.x + threadIdx.x) >> 5;
    int lane = threadIdx.x & 31;
    if (w >= N_EDGES) return;
    int src = ei[w];
    int dst = ei[N_EDGES + w];
    float4 v = x4[src * (D / 4) + lane];          // 512B coalesced row gather
    v.x = fmaxf(v.x, 0.f); v.y = fmaxf(v.y, 0.f);
    v.z = fmaxf(v.z, 0.f); v.w = fmaxf(v.w, 0.f);
    float* p = &g_agg[dst * D + lane * 4];
    asm volatile("red.global.add.v4.f32 [%0], {%1,%2,%3,%4};"
                 :: "l"(p), "f"(v.x), "f"(v.y), "f"(v.z), "f"(v.w) : "memory");
    if (lane == 0) atomicAdd(&g_cnt[dst], 1.0f);
}

// ---------------- kernel 3: fused mean + dual GEMM + bias + BN partial stats ----------------
// out[n,j] = sum_k agg[n,k]/max(cnt,1) * Wl[j,k] + sum_k relu(x[n,k]) * Wr[j,k] + bl[j]
// Shared layout: Ws[K2][D] (128KB) | As[TM][AS_STRIDE] (65KB) | redS[8][D] | redQ[8][D]
__global__ void gemm_kernel(const float* __restrict__ x,
                            const float* __restrict__ Wl,
                            const float* __restrict__ bl,
                            const float* __restrict__ Wr,
                            float* __restrict__ out) {
    extern __shared__ float sm[];
    float* Ws   = sm;                          // K2*D = 32768 floats
    float* As   = Ws + K2 * D;                 // TM*AS_STRIDE = 16640 floats
    float* redS = As + TM * AS_STRIDE;         // 8*D
    float* redQ = redS + 8 * D;                // 8*D

    const int tid = threadIdx.x;

    // Load weights transposed into shared: Ws[k][j]
    for (int i = tid; i < D * D; i += blockDim.x) {
        int j = i / D, k = i % D;
        Ws[k * D + j]       = Wl[i];
        Ws[(k + D) * D + j] = Wr[i];
    }
    __syncthreads();

    const int tx = tid & 31;       // feature group: j0 = tx*4 (whole warp shares ty)
    const int ty = tid >> 5;       // row group: rows ty*8 .. ty*8+7
    const int j0 = tx * 4;
    const float4 bias = *reinterpret_cast<const float4*>(bl + j0);

    const int ntiles = (N_NODES + TM - 1) / TM;
    for (int t = blockIdx.x; t < ntiles; t += gridDim.x) {
        const int row0 = t * TM;

        // ---- cooperative A-tile load: As[r][k] ----
        for (int i = tid; i < TM * (K2 / 4); i += blockDim.x) {
            int r  = i >> 6;         // 64 float4 per row
            int c4 = i & 63;
            int n  = row0 + r;
            float4 v = make_float4(0.f, 0.f, 0.f, 0.f);
            if (n < N_NODES) {
                if (c4 < 32) {       // mean-aggregated neighbors
                    float inv = 1.0f / fmaxf(g_cnt[n], 1.0f);
                    float4 a = *reinterpret_cast<const float4*>(&g_agg[n * D + c4 * 4]);
                    v.x = a.x * inv; v.y = a.y * inv; v.z = a.z * inv; v.w = a.w * inv;
                } else {             // relu(x) root term
                    float4 h = *reinterpret_cast<const float4*>(&x[n * D + (c4 - 32) * 4]);
                    v.x = fmaxf(h.x, 0.f); v.y = fmaxf(h.y, 0.f);
                    v.z = fmaxf(h.z, 0.f); v.w = fmaxf(h.w, 0.f);
                }
            }
            *reinterpret_cast<float4*>(&As[r * AS_STRIDE + c4 * 4]) = v;
        }
        __syncthreads();

        // ---- 8 rows x 4 cols register-blocked FFMA mainloop ----
        float acc[8][4];
        #pragma unroll
        for (int rr = 0; rr < 8; rr++)
            #pragma unroll
            for (int c = 0; c < 4; c++) acc[rr][c] = 0.f;

        const float* Arow = &As[(ty * 8) * AS_STRIDE];
        for (int k = 0; k < K2; k += 4) {   // body kept rolled: fits L0 I$
            float4 w0 = *reinterpret_cast<const float4*>(&Ws[(k + 0) * D + j0]);
            float4 w1 = *reinterpret_cast<const float4*>(&Ws[(k + 1) * D + j0]);
            float4 w2 = *reinterpret_cast<const float4*>(&Ws[(k + 2) * D + j0]);
            float4 w3 = *reinterpret_cast<const float4*>(&Ws[(k + 3) * D + j0]);
            #pragma unroll
            for (int rr = 0; rr < 8; rr++) {
                float4 a = *reinterpret_cast<const float4*>(&Arow[rr * AS_STRIDE + k]);
                acc[rr][0] += a.x * w0.x + a.y * w1.x + a.z * w2.x + a.w * w3.x;
                acc[rr][1] += a.x * w0.y + a.y * w1.y + a.z * w2.y + a.w * w3.y;
                acc[rr][2] += a.x * w0.z + a.y * w1.z + a.z * w2.z + a.w * w3.z;
                acc[rr][3] += a.x * w0.w + a.y * w1.w + a.z * w2.w + a.w * w3.w;
            }
        }

        // ---- epilogue: bias, store, per-feature partial BN stats ----
        float ps[4] = {0.f, 0.f, 0.f, 0.f};
        float pq[4] = {0.f, 0.f, 0.f, 0.f};
        #pragma unroll
        for (int rr = 0; rr < 8; rr++) {
            int n = row0 + ty * 8 + rr;
            if (n < N_NODES) {
                float4 o;
                o.x = acc[rr][0] + bias.x; o.y = acc[rr][1] + bias.y;
                o.z = acc[rr][2] + bias.z; o.w = acc[rr][3] + bias.w;
                *reinterpret_cast<float4*>(&out[n * D + j0]) = o;
                ps[0] += o.x; ps[1] += o.y; ps[2] += o.z; ps[3] += o.w;
                pq[0] += o.x * o.x; pq[1] += o.y * o.y;
                pq[2] += o.z * o.z; pq[3] += o.w * o.w;
            }
        }
        *reinterpret_cast<float4*>(&redS[ty * D + j0]) = make_float4(ps[0], ps[1], ps[2], ps[3]);
        *reinterpret_cast<float4*>(&redQ[ty * D + j0]) = make_float4(pq[0], pq[1], pq[2], pq[3]);
        __syncthreads();
        if (ty == 0) {
            float s[4] = {0.f, 0.f, 0.f, 0.f};
            float q[4] = {0.f, 0.f, 0.f, 0.f};
            #pragma unroll
            for (int u = 0; u < 8; u++) {
                float4 a = *reinterpret_cast<const float4*>(&redS[u * D + j0]);
                float4 b = *reinterpret_cast<const float4*>(&redQ[u * D + j0]);
                s[0] += a.x; s[1] += a.y; s[2] += a.z; s[3] += a.w;
                q[0] += b.x; q[1] += b.y; q[2] += b.z; q[3] += b.w;
            }
            atomicAdd(&g_sum[j0 + 0], s[0]); atomicAdd(&g_sum[j0 + 1], s[1]);
            atomicAdd(&g_sum[j0 + 2], s[2]); atomicAdd(&g_sum[j0 + 3], s[3]);
            atomicAdd(&g_sumsq[j0 + 0], q[0]); atomicAdd(&g_sumsq[j0 + 1], q[1]);
            atomicAdd(&g_sumsq[j0 + 2], q[2]); atomicAdd(&g_sumsq[j0 + 3], q[3]);
        }
        __syncthreads();   // protect red buffers / As before next tile
    }
}

// ---------------- kernel 4: batchnorm normalize ----------------
__global__ void bn_kernel(const float* __restrict__ gamma,
                          const float* __restrict__ beta,
                          float* __restrict__ out) {
    __shared__ float sscale[D];
    __shared__ float sshift[D];
    int tid = threadIdx.x;
    if (tid < D) {
        float mu  = g_sum[tid] * (1.0f / N_NODES);
        float var = g_sumsq[tid] * (1.0f / N_NODES) - mu * mu;   // biased, matches ref
        float sc  = gamma[tid] * rsqrtf(var + BN_EPS);
        sscale[tid] = sc;
        sshift[tid] = beta[tid] - mu * sc;
    }
    __syncthreads();
    const int total = N_NODES * (D / 4);
    float4* o4 = reinterpret_cast<float4*>(out);
    for (int i = blockIdx.x * blockDim.x + tid; i < total; i += gridDim.x * blockDim.x) {
        int c4 = i & 31;
        float4 v  = o4[i];
        float4 sc = *reinterpret_cast<const float4*>(&sscale[c4 * 4]);
        float4 sh = *reinterpret_cast<const float4*>(&sshift[c4 * 4]);
        v.x = v.x * sc.x + sh.x; v.y = v.y * sc.y + sh.y;
        v.z = v.z * sc.z + sh.z; v.w = v.w * sc.w + sh.w;
        o4[i] = v;
    }
}

// ---------------- launch ----------------
extern "C" void kernel_launch(void* const* d_in, const int* in_sizes, int n_in,
                              void* d_out, int out_size) {
    // metadata order: x, edge_attr, W_l, b_l, W_r, gamma, beta, edge_index
    const float* x     = (const float*)d_in[0];
    const float* Wl    = (const float*)d_in[2];
    const float* bl    = (const float*)d_in[3];
    const float* Wr    = (const float*)d_in[4];
    const float* gamma = (const float*)d_in[5];
    const float* beta  = (const float*)d_in[6];
    const int*   ei    = (const int*)d_in[7];
    float* out = (float*)d_out;

    static bool attr_done = false;
    const int gemm_smem = (K2 * D + TM * AS_STRIDE + 16 * D) * (int)sizeof(float); // 205824 B
    if (!attr_done) {
        cudaFuncSetAttribute(gemm_kernel, cudaFuncAttributeMaxDynamicSharedMemorySize, gemm_smem);
        attr_done = true;
    }

    zero_kernel<<<4096, 256>>>();
    scatter_kernel<<<(N_EDGES * 32) / 256, 256>>>((const float4*)x, ei);
    gemm_kernel<<<148, 256, gemm_smem>>>(x, Wl, bl, Wr, out);
    bn_kernel<<<2048, 256>>>(gamma, beta, out);
}

// round 4
// speedup vs baseline: 1.0644x; 1.0644x over previous
#include <cuda_runtime.h>
#include <cuda_bf16.h>
#include <cstdint>

#define N_NODES 100000
#define N_EDGES 640000
#define D       128
#define BN_EPS  1e-5f
#define TM      128
#define NTILES  ((N_NODES + TM - 1) / TM)   // 782

// ==================== scratch ====================
__device__ float g_agg[N_NODES * D];
__device__ float g_cnt[N_NODES];
__device__ float g_sum[D];
__device__ float g_sumsq[D];

// ==================== helpers ====================
__device__ __forceinline__ uint32_t smem_to_u32(const void* p) {
    uint32_t a;
    asm("{ .reg .u64 t; cvta.to.shared.u64 t, %1; cvt.u32.u64 %0, t; }" : "=r"(a) : "l"(p));
    return a;
}
#define LDSM_X4(r0, r1, r2, r3, addr) \
    asm volatile("ldmatrix.sync.aligned.m8n8.x4.shared.b16 {%0,%1,%2,%3}, [%4];" \
        : "=r"(r0), "=r"(r1), "=r"(r2), "=r"(r3) : "r"(addr))
#define MMA_BF16(c, a, b0, b1) \
    asm volatile("mma.sync.aligned.m16n8k16.row.col.f32.bf16.bf16.f32 " \
        "{%0,%1,%2,%3}, {%4,%5,%6,%7}, {%8,%9}, {%0,%1,%2,%3};" \
        : "+f"((c)[0]), "+f"((c)[1]), "+f"((c)[2]), "+f"((c)[3]) \
        : "r"((a)[0]), "r"((a)[1]), "r"((a)[2]), "r"((a)[3]), "r"(b0), "r"(b1))

// ==================== kernel 1: zero scratch ====================
__global__ void zero_kernel() {
    const int stride = gridDim.x * blockDim.x;
    int i = blockIdx.x * blockDim.x + threadIdx.x;
    float4 z = make_float4(0.f, 0.f, 0.f, 0.f);
    float4* a4 = reinterpret_cast<float4*>(g_agg);
    const int nAgg4 = (N_NODES * D) / 4;
    for (int idx = i; idx < nAgg4; idx += stride) a4[idx] = z;
    float4* c4 = reinterpret_cast<float4*>(g_cnt);
    for (int idx = i; idx < N_NODES / 4; idx += stride) c4[idx] = z;
    if (i < D) { g_sum[i] = 0.f; g_sumsq[i] = 0.f; }
}

// ==================== kernel 2: edge scatter ====================
__global__ void scatter_kernel(const float4* __restrict__ x4,
                               const int* __restrict__ ei) {
    int w    = (blockIdx.x * blockDim.x + threadIdx.x) >> 5;
    int lane = threadIdx.x & 31;
    if (w >= N_EDGES) return;
    int src = ei[w];
    int dst = ei[N_EDGES + w];
    float4 v = x4[src * (D / 4) + lane];
    v.x = fmaxf(v.x, 0.f); v.y = fmaxf(v.y, 0.f);
    v.z = fmaxf(v.z, 0.f); v.w = fmaxf(v.w, 0.f);
    float* p = &g_agg[dst * D + lane * 4];
    asm volatile("red.global.add.v4.f32 [%0], {%1,%2,%3,%4};"
                 :: "l"(p), "f"(v.x), "f"(v.y), "f"(v.z), "f"(v.w) : "memory");
    if (lane == 0) atomicAdd(&g_cnt[dst], 1.0f);
}

// ==================== kernel 3: bf16 hi/lo mma.sync GEMM ====================
// out[100000,128] = A[100000,256] @ Wcat^T   (A = [mean_agg | relu(x)], Wcat = [Wl | Wr])
// Bias b_l omitted: BatchNorm cancels per-column bias exactly.
// SMEM: A_hi[128][128]h (32KB) | A_lo (32KB) | W_hi[128][256]h (64KB) | W_lo (64KB) = 192KB
#define SM_AHI 0
#define SM_ALO 32768
#define SM_WHI 65536
#define SM_WLO 131072
#define SM_TOTAL 196608

// XOR swizzles (16B chunk granularity) for conflict-free ldmatrix
__device__ __forceinline__ uint32_t aoff(int r, int c) {       // A: stride 256B, c in [0,16)
    return (uint32_t)(r * 256 + (((c & 8) | ((c ^ (r & 7)) & 7)) << 4));
}
__device__ __forceinline__ uint32_t woff(int j, int c) {       // W: stride 512B, c in [0,32)
    return (uint32_t)(j * 512 + (((c & 24) | ((c ^ (j & 7)) & 7)) << 4));
}
__device__ __forceinline__ void split_row8(const float4& f0, const float4& f1,
                                           uint4& hi, uint4& lo) {
    __nv_bfloat162 h0 = __floats2bfloat162_rn(f0.x, f0.y);
    __nv_bfloat162 h1 = __floats2bfloat162_rn(f0.z, f0.w);
    __nv_bfloat162 h2 = __floats2bfloat162_rn(f1.x, f1.y);
    __nv_bfloat162 h3 = __floats2bfloat162_rn(f1.z, f1.w);
    float2 g0 = __bfloat1622float2(h0), g1 = __bfloat1622float2(h1);
    float2 g2 = __bfloat1622float2(h2), g3 = __bfloat1622float2(h3);
    __nv_bfloat162 l0 = __floats2bfloat162_rn(f0.x - g0.x, f0.y - g0.y);
    __nv_bfloat162 l1 = __floats2bfloat162_rn(f0.z - g1.x, f0.w - g1.y);
    __nv_bfloat162 l2 = __floats2bfloat162_rn(f1.x - g2.x, f1.y - g2.y);
    __nv_bfloat162 l3 = __floats2bfloat162_rn(f1.z - g3.x, f1.w - g3.y);
    hi = make_uint4(*(uint32_t*)&h0, *(uint32_t*)&h1, *(uint32_t*)&h2, *(uint32_t*)&h3);
    lo = make_uint4(*(uint32_t*)&l0, *(uint32_t*)&l1, *(uint32_t*)&l2, *(uint32_t*)&l3);
}

__global__ void __launch_bounds__(128, 1)
gemm_mma_kernel(const float* __restrict__ x,
                const float* __restrict__ Wl,
                const float* __restrict__ Wr,
                float* __restrict__ out) {
    extern __shared__ char smem[];
    const uint32_t sb = smem_to_u32(smem);
    const int tid  = threadIdx.x;
    const int lane = tid & 31;
    const int wid  = tid >> 5;

    // ---- W conversion: row j = tid, 32 chunks of 8 halves ----
    {
        const int j = tid;
        #pragma unroll 4
        for (int c = 0; c < 32; c++) {
            const float* src = (c < 16) ? &Wl[j * 128 + c * 8] : &Wr[j * 128 + (c - 16) * 8];
            float4 f0 = *reinterpret_cast<const float4*>(src);
            float4 f1 = *reinterpret_cast<const float4*>(src + 4);
            uint4 hi, lo;
            split_row8(f0, f1, hi, lo);
            uint32_t o = woff(j, c);
            *reinterpret_cast<uint4*>(smem + SM_WHI + o) = hi;
            *reinterpret_cast<uint4*>(smem + SM_WLO + o) = lo;
        }
    }

    // ldmatrix lane-address components
    const int a_row = wid * 32 + (lane & 15);          // + mt*16
    const int a_rx  = a_row & 7;
    const int a_csel = lane >> 4;                      // chunk low bit
    const int b_jsub = (lane & 7) + ((lane >> 4) << 3);// row within 16-row n-pair
    const int b_jx  = lane & 7;
    const int b_csel = (lane >> 3) & 1;

    float c[2][16][4];

    for (int t = blockIdx.x; t < NTILES; t += gridDim.x) {
        const int row0 = t * TM;
        #pragma unroll
        for (int mt = 0; mt < 2; mt++)
            #pragma unroll
            for (int nt = 0; nt < 16; nt++)
                #pragma unroll
                for (int q = 0; q < 4; q++) c[mt][nt][q] = 0.f;

        #pragma unroll 1
        for (int kh = 0; kh < 2; kh++) {
            __syncthreads();     // previous consumers done before A overwrite
            // ---- A prep: row r = tid ----
            {
                const int r = tid;
                const int n = row0 + r;
                const bool valid = (n < N_NODES);
                float inv = 1.0f;
                const float* srow;
                if (kh == 0) {
                    srow = &g_agg[(valid ? n : 0) * D];
                    if (valid) inv = 1.0f / fmaxf(g_cnt[n], 1.0f);
                } else {
                    srow = &x[(valid ? n : 0) * D];
                }
                #pragma unroll 4
                for (int cc = 0; cc < 16; cc++) {
                    float4 f0 = make_float4(0.f, 0.f, 0.f, 0.f), f1 = f0;
                    if (valid) {
                        f0 = *reinterpret_cast<const float4*>(srow + cc * 8);
                        f1 = *reinterpret_cast<const float4*>(srow + cc * 8 + 4);
                        if (kh == 0) {
                            f0.x *= inv; f0.y *= inv; f0.z *= inv; f0.w *= inv;
                            f1.x *= inv; f1.y *= inv; f1.z *= inv; f1.w *= inv;
                        } else {
                            f0.x = fmaxf(f0.x, 0.f); f0.y = fmaxf(f0.y, 0.f);
                            f0.z = fmaxf(f0.z, 0.f); f0.w = fmaxf(f0.w, 0.f);
                            f1.x = fmaxf(f1.x, 0.f); f1.y = fmaxf(f1.y, 0.f);
                            f1.z = fmaxf(f1.z, 0.f); f1.w = fmaxf(f1.w, 0.f);
                        }
                    }
                    uint4 hi, lo;
                    split_row8(f0, f1, hi, lo);
                    uint32_t o = aoff(r, cc);
                    *reinterpret_cast<uint4*>(smem + SM_AHI + o) = hi;
                    *reinterpret_cast<uint4*>(smem + SM_ALO + o) = lo;
                }
            }
            __syncthreads();

            // ---- compute: 3 passes x 8 k-steps over this K-half ----
            #pragma unroll 1
            for (int pass = 0; pass < 3; pass++) {
                const uint32_t Ab = sb + ((pass < 2) ? SM_AHI : SM_ALO);
                const uint32_t Wb = sb + ((pass == 1) ? SM_WLO : SM_WHI);
                #pragma unroll 1
                for (int ks = 0; ks < 8; ks++) {
                    const int kc = 2 * ks;             // base chunk within half
                    uint32_t a0[4], a1[4];
                    {
                        int cA = kc + a_csel;
                        LDSM_X4(a0[0], a0[1], a0[2], a0[3], Ab + aoff(a_row,      cA));
                        LDSM_X4(a1[0], a1[1], a1[2], a1[3], Ab + aoff(a_row + 16, cA));
                    }
                    const int cW = kh * 16 + kc + b_csel;
                    const uint32_t wsw = (uint32_t)((((cW & 24) | ((cW ^ b_jx) & 7)) << 4));
                    #pragma unroll
                    for (int np = 0; np < 8; np++) {
                        uint32_t b[4];
                        uint32_t baddr = Wb + (uint32_t)((np * 16 + b_jsub) * 512) + wsw;
                        LDSM_X4(b[0], b[1], b[2], b[3], baddr);
                        MMA_BF16(c[0][2 * np],     a0, b[0], b[1]);
                        MMA_BF16(c[0][2 * np + 1], a0, b[2], b[3]);
                        MMA_BF16(c[1][2 * np],     a1, b[0], b[1]);
                        MMA_BF16(c[1][2 * np + 1], a1, b[2], b[3]);
                    }
                }
            }
        }

        // ---- epilogue: direct float2 stores (no bias — BN cancels it) ----
        const int qrow = lane >> 2;
        const int qcol = (lane & 3) * 2;
        #pragma unroll
        for (int mt = 0; mt < 2; mt++) {
            const int r_lo = row0 + wid * 32 + mt * 16 + qrow;
            #pragma unroll
            for (int nt = 0; nt < 16; nt++) {
                const int col = nt * 8 + qcol;
                if (r_lo < N_NODES)
                    *reinterpret_cast<float2*>(&out[r_lo * D + col]) =
                        make_float2(c[mt][nt][0], c[mt][nt][1]);
                if (r_lo + 8 < N_NODES)
                    *reinterpret_cast<float2*>(&out[(r_lo + 8) * D + col]) =
                        make_float2(c[mt][nt][2], c[mt][nt][3]);
            }
        }
    }
}

// ==================== kernel 4: BN stats ====================
__global__ void stats_kernel(const float* __restrict__ out) {
    const int tid = threadIdx.x;
    const int c4 = tid & 31;               // stride ≡ 0 (mod 32) keeps this fixed
    float ps[4] = {0.f, 0.f, 0.f, 0.f};
    float pq[4] = {0.f, 0.f, 0.f, 0.f};
    const float4* o4 = reinterpret_cast<const float4*>(out);
    const int total = N_NODES * (D / 4);
    for (int i = blockIdx.x * blockDim.x + tid; i < total; i += gridDim.x * blockDim.x) {
        float4 v = o4[i];
        ps[0] += v.x; ps[1] += v.y; ps[2] += v.z; ps[3] += v.w;
        pq[0] += v.x * v.x; pq[1] += v.y * v.y; pq[2] += v.z * v.z; pq[3] += v.w * v.w;
    }
    #pragma unroll
    for (int j = 0; j < 4; j++) {
        atomicAdd(&g_sum[c4 * 4 + j], ps[j]);
        atomicAdd(&g_sumsq[c4 * 4 + j], pq[j]);
    }
}

// ==================== kernel 5: batchnorm normalize ====================
__global__ void bn_kernel(const float* __restrict__ gamma,
                          const float* __restrict__ beta,
                          float* __restrict__ out) {
    __shared__ float sscale[D];
    __shared__ float sshift[D];
    int tid = threadIdx.x;
    if (tid < D) {
        float mu  = g_sum[tid] * (1.0f / N_NODES);
        float var = g_sumsq[tid] * (1.0f / N_NODES) - mu * mu;
        float sc  = gamma[tid] * rsqrtf(var + BN_EPS);
        sscale[tid] = sc;
        sshift[tid] = beta[tid] - mu * sc;
    }
    __syncthreads();
    const int total = N_NODES * (D / 4);
    float4* o4 = reinterpret_cast<float4*>(out);
    for (int i = blockIdx.x * blockDim.x + tid; i < total; i += gridDim.x * blockDim.x) {
        int c4 = i & 31;
        float4 v  = o4[i];
        float4 sc = *reinterpret_cast<const float4*>(&sscale[c4 * 4]);
        float4 sh = *reinterpret_cast<const float4*>(&sshift[c4 * 4]);
        v.x = v.x * sc.x + sh.x; v.y = v.y * sc.y + sh.y;
        v.z = v.z * sc.z + sh.z; v.w = v.w * sc.w + sh.w;
        o4[i] = v;
    }
}

// ==================== launch ====================
extern "C" void kernel_launch(void* const* d_in, const int* in_sizes, int n_in,
                              void* d_out, int out_size) {
    const float* x     = (const float*)d_in[0];
    const float* Wl    = (const float*)d_in[2];
    const float* Wr    = (const float*)d_in[4];
    const float* gamma = (const float*)d_in[5];
    const float* beta  = (const float*)d_in[6];
    const int*   ei    = (const int*)d_in[7];
    float* out = (float*)d_out;

    static bool attr_done = false;
    if (!attr_done) {
        cudaFuncSetAttribute(gemm_mma_kernel,
                             cudaFuncAttributeMaxDynamicSharedMemorySize, SM_TOTAL);
        attr_done = true;
    }

    zero_kernel<<<4096, 256>>>();
    scatter_kernel<<<(N_EDGES * 32) / 256, 256>>>((const float4*)x, ei);
    gemm_mma_kernel<<<148, 128, SM_TOTAL>>>(x, Wl, Wr, out);
    stats_kernel<<<512, 256>>>(out);
    bn_kernel<<<2048, 256>>>(gamma, beta, out);
}

// round 6
// speedup vs baseline: 1.1502x; 1.0806x over previous
#include <cuda_runtime.h>
#include <cuda_bf16.h>
#include <cstdint>

#define N_NODES 100000
#define N_EDGES 640000
#define D       128
#define BN_EPS  1e-5f
#define TM      128
#define NTILES  ((N_NODES + TM - 1) / TM)   // 782

// ==================== scratch ====================
__device__ float g_agg[N_NODES * D];      // mean-aggregated relu(x[src]) per node
__device__ int   g_deg[N_NODES];
__device__ int   g_rowptr[N_NODES + 1];
__device__ int   g_woff[N_NODES];
__device__ int   g_src[N_EDGES];
__device__ float g_sum[D];
__device__ float g_sumsq[D];

// ==================== helpers ====================
__device__ __forceinline__ uint32_t smem_to_u32(const void* p) {
    uint32_t a;
    asm("{ .reg .u64 t; cvta.to.shared.u64 t, %1; cvt.u32.u64 %0, t; }" : "=r"(a) : "l"(p));
    return a;
}
#define LDSM_X4(r0, r1, r2, r3, addr) \
    asm volatile("ldmatrix.sync.aligned.m8n8.x4.shared.b16 {%0,%1,%2,%3}, [%4];" \
        : "=r"(r0), "=r"(r1), "=r"(r2), "=r"(r3) : "r"(addr))
#define MMA_BF16(c, a, b0, b1) \
    asm volatile("mma.sync.aligned.m16n8k16.row.col.f32.bf16.bf16.f32 " \
        "{%0,%1,%2,%3}, {%4,%5,%6,%7}, {%8,%9}, {%0,%1,%2,%3};" \
        : "+f"((c)[0]), "+f"((c)[1]), "+f"((c)[2]), "+f"((c)[3]) \
        : "r"((a)[0]), "r"((a)[1]), "r"((a)[2]), "r"((a)[3]), "r"(b0), "r"(b1))

// ==================== kernel 1: zero degree + BN accumulators ====================
__global__ void zero_kernel() {
    int i = blockIdx.x * blockDim.x + threadIdx.x;
    const int stride = gridDim.x * blockDim.x;
    for (int idx = i; idx < N_NODES; idx += stride) g_deg[idx] = 0;
    if (i < D) { g_sum[i] = 0.f; g_sumsq[i] = 0.f; }
}

// ==================== kernel 2: degree histogram ====================
__global__ void hist_kernel(const int* __restrict__ ei) {
    int i = blockIdx.x * blockDim.x + threadIdx.x;
    if (i < N_EDGES) atomicAdd(&g_deg[ei[N_EDGES + i]], 1);
}

// ==================== kernel 3: exclusive prefix scan (single block) ====================
#define SCAN_T 1024
#define CHUNK  98                     // 1024*98 = 100352 >= 100000
__global__ void scan_kernel() {
    __shared__ int spart[SCAN_T];
    const int t = threadIdx.x;
    const int lo = t * CHUNK;
    const int hi = min(lo + CHUNK, N_NODES);
    int local = 0;
    for (int i = lo; i < hi; i++) local += g_deg[i];
    spart[t] = local;
    __syncthreads();
    for (int off = 1; off < SCAN_T; off <<= 1) {      // Hillis-Steele inclusive
        int v = (t >= off) ? spart[t - off] : 0;
        __syncthreads();
        spart[t] += v;
        __syncthreads();
    }
    int run = spart[t] - local;       // exclusive base for this chunk
    for (int i = lo; i < hi; i++) {
        g_rowptr[i] = run;
        g_woff[i]   = run;
        run += g_deg[i];
    }
    if (t == SCAN_T - 1) g_rowptr[N_NODES] = N_EDGES;
}

// ==================== kernel 4: fill sorted src lists ====================
__global__ void fill_kernel(const int* __restrict__ ei) {
    int i = blockIdx.x * blockDim.x + threadIdx.x;
    if (i < N_EDGES) {
        int pos = atomicAdd(&g_woff[ei[N_EDGES + i]], 1);
        g_src[pos] = ei[i];
    }
}

// ==================== kernel 5: CSR mean aggregation (one warp per node, MLP=4) ====================
__global__ void agg_kernel(const float4* __restrict__ x4) {
    const int w    = (blockIdx.x * blockDim.x + threadIdx.x) >> 5;
    const int lane = threadIdx.x & 31;
    if (w >= N_NODES) return;
    const int start = g_rowptr[w];
    const int end   = g_rowptr[w + 1];
    float4 acc = make_float4(0.f, 0.f, 0.f, 0.f);
    int e = start;
    for (; e + 3 < end; e += 4) {
        int s0 = g_src[e], s1 = g_src[e + 1], s2 = g_src[e + 2], s3 = g_src[e + 3];
        float4 v0 = x4[s0 * 32 + lane];
        float4 v1 = x4[s1 * 32 + lane];
        float4 v2 = x4[s2 * 32 + lane];
        float4 v3 = x4[s3 * 32 + lane];
        acc.x += fmaxf(v0.x, 0.f) + fmaxf(v1.x, 0.f) + fmaxf(v2.x, 0.f) + fmaxf(v3.x, 0.f);
        acc.y += fmaxf(v0.y, 0.f) + fmaxf(v1.y, 0.f) + fmaxf(v2.y, 0.f) + fmaxf(v3.y, 0.f);
        acc.z += fmaxf(v0.z, 0.f) + fmaxf(v1.z, 0.f) + fmaxf(v2.z, 0.f) + fmaxf(v3.z, 0.f);
        acc.w += fmaxf(v0.w, 0.f) + fmaxf(v1.w, 0.f) + fmaxf(v2.w, 0.f) + fmaxf(v3.w, 0.f);
    }
    for (; e < end; e++) {
        float4 v0 = x4[g_src[e] * 32 + lane];
        acc.x += fmaxf(v0.x, 0.f); acc.y += fmaxf(v0.y, 0.f);
        acc.z += fmaxf(v0.z, 0.f); acc.w += fmaxf(v0.w, 0.f);
    }
    const float inv = 1.0f / (float)max(end - start, 1);
    acc.x *= inv; acc.y *= inv; acc.z *= inv; acc.w *= inv;
    reinterpret_cast<float4*>(g_agg)[w * 32 + lane] = acc;
}

// ==================== kernel 6: bf16 hi/lo mma.sync GEMM ====================
// out[100000,128] = A[100000,256] @ Wcat^T   (A = [g_agg | relu(x)], Wcat = [Wl | Wr])
// Bias b_l omitted: BatchNorm cancels per-column bias exactly.
#define SM_AHI 0
#define SM_ALO 32768
#define SM_WHI 65536
#define SM_WLO 131072
#define SM_TOTAL 196608

__device__ __forceinline__ uint32_t aoff(int r, int c) {       // A: stride 256B, c in [0,16)
    return (uint32_t)(r * 256 + (((c & 8) | ((c ^ (r & 7)) & 7)) << 4));
}
__device__ __forceinline__ uint32_t woff_sw(int j, int c) {    // W: stride 512B, c in [0,32)
    return (uint32_t)(j * 512 + (((c & 24) | ((c ^ (j & 7)) & 7)) << 4));
}
__device__ __forceinline__ void split_row8(const float4& f0, const float4& f1,
                                           uint4& hi, uint4& lo) {
    __nv_bfloat162 h0 = __floats2bfloat162_rn(f0.x, f0.y);
    __nv_bfloat162 h1 = __floats2bfloat162_rn(f0.z, f0.w);
    __nv_bfloat162 h2 = __floats2bfloat162_rn(f1.x, f1.y);
    __nv_bfloat162 h3 = __floats2bfloat162_rn(f1.z, f1.w);
    float2 g0 = __bfloat1622float2(h0), g1 = __bfloat1622float2(h1);
    float2 g2 = __bfloat1622float2(h2), g3 = __bfloat1622float2(h3);
    __nv_bfloat162 l0 = __floats2bfloat162_rn(f0.x - g0.x, f0.y - g0.y);
    __nv_bfloat162 l1 = __floats2bfloat162_rn(f0.z - g1.x, f0.w - g1.y);
    __nv_bfloat162 l2 = __floats2bfloat162_rn(f1.x - g2.x, f1.y - g2.y);
    __nv_bfloat162 l3 = __floats2bfloat162_rn(f1.z - g3.x, f1.w - g3.y);
    hi = make_uint4(*(uint32_t*)&h0, *(uint32_t*)&h1, *(uint32_t*)&h2, *(uint32_t*)&h3);
    lo = make_uint4(*(uint32_t*)&l0, *(uint32_t*)&l1, *(uint32_t*)&l2, *(uint32_t*)&l3);
}

__global__ void __launch_bounds__(128, 1)
gemm_mma_kernel(const float* __restrict__ x,
                const float* __restrict__ Wl,
                const float* __restrict__ Wr,
                float* __restrict__ out) {
    extern __shared__ char smem[];
    const uint32_t sb = smem_to_u32(smem);
    const int tid  = threadIdx.x;
    const int lane = tid & 31;
    const int wid  = tid >> 5;

    // ---- W conversion: row j = tid, 32 chunks of 8 halves ----
    {
        const int j = tid;
        #pragma unroll 4
        for (int c = 0; c < 32; c++) {
            const float* src = (c < 16) ? &Wl[j * 128 + c * 8] : &Wr[j * 128 + (c - 16) * 8];
            float4 f0 = *reinterpret_cast<const float4*>(src);
            float4 f1 = *reinterpret_cast<const float4*>(src + 4);
            uint4 hi, lo;
            split_row8(f0, f1, hi, lo);
            uint32_t o = woff_sw(j, c);
            *reinterpret_cast<uint4*>(smem + SM_WHI + o) = hi;
            *reinterpret_cast<uint4*>(smem + SM_WLO + o) = lo;
        }
    }

    const int a_row  = wid * 32 + (lane & 15);
    const int a_csel = lane >> 4;
    const int b_jsub = (lane & 7) + ((lane >> 4) << 3);
    const int b_jx   = lane & 7;
    const int b_csel = (lane >> 3) & 1;

    float c[2][16][4];

    for (int t = blockIdx.x; t < NTILES; t += gridDim.x) {
        const int row0 = t * TM;
        #pragma unroll
        for (int mt = 0; mt < 2; mt++)
            #pragma unroll
            for (int nt = 0; nt < 16; nt++)
                #pragma unroll
                for (int q = 0; q < 4; q++) c[mt][nt][q] = 0.f;

        #pragma unroll 1
        for (int kh = 0; kh < 2; kh++) {
            __syncthreads();
            // ---- A prep: row r = tid ----
            {
                const int r = tid;
                const int n = row0 + r;
                const bool valid = (n < N_NODES);
                const float* srow = (kh == 0) ? &g_agg[(valid ? n : 0) * D]
                                              : &x[(valid ? n : 0) * D];
                #pragma unroll 4
                for (int cc = 0; cc < 16; cc++) {
                    float4 f0 = make_float4(0.f, 0.f, 0.f, 0.f), f1 = f0;
                    if (valid) {
                        f0 = *reinterpret_cast<const float4*>(srow + cc * 8);
                        f1 = *reinterpret_cast<const float4*>(srow + cc * 8 + 4);
                        if (kh == 1) {
                            f0.x = fmaxf(f0.x, 0.f); f0.y = fmaxf(f0.y, 0.f);
                            f0.z = fmaxf(f0.z, 0.f); f0.w = fmaxf(f0.w, 0.f);
                            f1.x = fmaxf(f1.x, 0.f); f1.y = fmaxf(f1.y, 0.f);
                            f1.z = fmaxf(f1.z, 0.f); f1.w = fmaxf(f1.w, 0.f);
                        }
                    }
                    uint4 hi, lo;
                    split_row8(f0, f1, hi, lo);
                    uint32_t o = aoff(r, cc);
                    *reinterpret_cast<uint4*>(smem + SM_AHI + o) = hi;
                    *reinterpret_cast<uint4*>(smem + SM_ALO + o) = lo;
                }
            }
            __syncthreads();

            // ---- compute: 3 passes x 8 k-steps over this K-half ----
            #pragma unroll 1
            for (int pass = 0; pass < 3; pass++) {
                const uint32_t Ab = sb + ((pass < 2) ? SM_AHI : SM_ALO);
                const uint32_t Wb = sb + ((pass == 1) ? SM_WLO : SM_WHI);
                #pragma unroll 1
                for (int ks = 0; ks < 8; ks++) {
                    const int kc = 2 * ks;
                    uint32_t a0[4], a1[4];
                    {
                        int cA = kc + a_csel;
                        LDSM_X4(a0[0], a0[1], a0[2], a0[3], Ab + aoff(a_row,      cA));
                        LDSM_X4(a1[0], a1[1], a1[2], a1[3], Ab + aoff(a_row + 16, cA));
                    }
                    const int cW = kh * 16 + kc + b_csel;
                    const uint32_t wsw = (uint32_t)((((cW & 24) | ((cW ^ b_jx) & 7)) << 4));
                    #pragma unroll
                    for (int np = 0; np < 8; np++) {
                        uint32_t b[4];
                        uint32_t baddr = Wb + (uint32_t)((np * 16 + b_jsub) * 512) + wsw;
                        LDSM_X4(b[0], b[1], b[2], b[3], baddr);
                        MMA_BF16(c[0][2 * np],     a0, b[0], b[1]);
                        MMA_BF16(c[0][2 * np + 1], a0, b[2], b[3]);
                        MMA_BF16(c[1][2 * np],     a1, b[0], b[1]);
                        MMA_BF16(c[1][2 * np + 1], a1, b[2], b[3]);
                    }
                }
            }
        }

        // ---- epilogue: direct float2 stores (no bias — BN cancels it) ----
        const int qrow = lane >> 2;
        const int qcol = (lane & 3) * 2;
        #pragma unroll
        for (int mt = 0; mt < 2; mt++) {
            const int r_lo = row0 + wid * 32 + mt * 16 + qrow;
            #pragma unroll
            for (int nt = 0; nt < 16; nt++) {
                const int col = nt * 8 + qcol;
                if (r_lo < N_NODES)
                    *reinterpret_cast<float2*>(&out[r_lo * D + col]) =
                        make_float2(c[mt][nt][0], c[mt][nt][1]);
                if (r_lo + 8 < N_NODES)
                    *reinterpret_cast<float2*>(&out[(r_lo + 8) * D + col]) =
                        make_float2(c[mt][nt][2], c[mt][nt][3]);
            }
        }
    }
}

// ==================== kernel 7: BN stats (block smem reduction -> few atomics) ====================
#define STAT_B 296
#define STAT_T 512
__global__ void stats_kernel(const float* __restrict__ out) {
    __shared__ float red[2 * D];
    const int tid = threadIdx.x;
    if (tid < 2 * D) red[tid] = 0.f;
    __syncthreads();
    const int c4 = tid & 31;              // fixed: stride is a multiple of 32
    float ps[4] = {0.f, 0.f, 0.f, 0.f};
    float pq[4] = {0.f, 0.f, 0.f, 0.f};
    const float4* o4 = reinterpret_cast<const float4*>(out);
    const int total = N_NODES * (D / 4);
    const int S = STAT_B * STAT_T;
    int i = blockIdx.x * STAT_T + tid;
    for (; i + 3 * S < total; i += 4 * S) {     // MLP=4
        float4 v0 = o4[i], v1 = o4[i + S], v2 = o4[i + 2 * S], v3 = o4[i + 3 * S];
        ps[0] += v0.x + v1.x + v2.x + v3.x;
        ps[1] += v0.y + v1.y + v2.y + v3.y;
        ps[2] += v0.z + v1.z + v2.z + v3.z;
        ps[3] += v0.w + v1.w + v2.w + v3.w;
        pq[0] += v0.x * v0.x + v1.x * v1.x + v2.x * v2.x + v3.x * v3.x;
        pq[1] += v0.y * v0.y + v1.y * v1.y + v2.y * v2.y + v3.y * v3.y;
        pq[2] += v0.z * v0.z + v1.z * v1.z + v2.z * v2.z + v3.z * v3.z;
        pq[3] += v0.w * v0.w + v1.w * v1.w + v2.w * v2.w + v3.w * v3.w;
    }
    for (; i < total; i += S) {
        float4 v = o4[i];
        ps[0] += v.x; ps[1] += v.y; ps[2] += v.z; ps[3] += v.w;
        pq[0] += v.x * v.x; pq[1] += v.y * v.y; pq[2] += v.z * v.z; pq[3] += v.w * v.w;
    }
    #pragma unroll
    for (int j = 0; j < 4; j++) {
        atomicAdd(&red[c4 * 4 + j], ps[j]);
        atomicAdd(&red[D + c4 * 4 + j], pq[j]);
    }
    __syncthreads();
    if (tid < D) {
        atomicAdd(&g_sum[tid], red[tid]);             // 296 contributions/address
        atomicAdd(&g_sumsq[tid], red[D + tid]);
    }
}

// ==================== kernel 8: batchnorm normalize ====================
__global__ void bn_kernel(const float* __restrict__ gamma,
                          const float* __restrict__ beta,
                          float* __restrict__ out) {
    __shared__ float sscale[D];
    __shared__ float sshift[D];
    int tid = threadIdx.x;
    if (tid < D) {
        float mu  = g_sum[tid] * (1.0f / N_NODES);
        float var = g_sumsq[tid] * (1.0f / N_NODES) - mu * mu;
        float sc  = gamma[tid] * rsqrtf(var + BN_EPS);
        sscale[tid] = sc;
        sshift[tid] = beta[tid] - mu * sc;
    }
    __syncthreads();
    const int total = N_NODES * (D / 4);
    float4* o4 = reinterpret_cast<float4*>(out);
    for (int i = blockIdx.x * blockDim.x + tid; i < total; i += gridDim.x * blockDim.x) {
        int c4 = i & 31;
        float4 v  = o4[i];
        float4 sc = *reinterpret_cast<const float4*>(&sscale[c4 * 4]);
        float4 sh = *reinterpret_cast<const float4*>(&sshift[c4 * 4]);
        v.x = v.x * sc.x + sh.x; v.y = v.y * sc.y + sh.y;
        v.z = v.z * sc.z + sh.z; v.w = v.w * sc.w + sh.w;
        o4[i] = v;
    }
}

// ==================== launch ====================
extern "C" void kernel_launch(void* const* d_in, const int* in_sizes, int n_in,
                              void* d_out, int out_size) {
    const float* x     = (const float*)d_in[0];
    const float* Wl    = (const float*)d_in[2];
    const float* Wr    = (const float*)d_in[4];
    const float* gamma = (const float*)d_in[5];
    const float* beta  = (const float*)d_in[6];
    const int*   ei    = (const int*)d_in[7];
    float* out = (float*)d_out;

    static bool attr_done = false;
    if (!attr_done) {
        cudaFuncSetAttribute(gemm_mma_kernel,
                             cudaFuncAttributeMaxDynamicSharedMemorySize, SM_TOTAL);
        attr_done = true;
    }

    zero_kernel<<<512, 256>>>();
    hist_kernel<<<(N_EDGES + 255) / 256, 256>>>(ei);
    scan_kernel<<<1, SCAN_T>>>();
    fill_kernel<<<(N_EDGES + 255) / 256, 256>>>(ei);
    agg_kernel<<<(N_NODES * 32 + 255) / 256, 256>>>((const float4*)x);
    gemm_mma_kernel<<<148, 128, SM_TOTAL>>>(x, Wl, Wr, out);
    stats_kernel<<<STAT_B, STAT_T>>>(out);
    bn_kernel<<<2048, 256>>>(gamma, beta, out);
}

// round 7
// speedup vs baseline: 1.5817x; 1.3751x over previous
#include <cuda_runtime.h>
#include <cuda_bf16.h>
#include <cstdint>

#define N_NODES 100000
#define N_EDGES 640000
#define D       128
#define BN_EPS  1e-5f
#define TM      128
#define NTILES  ((N_NODES + TM - 1) / TM)   // 782

// ==================== scratch ====================
__device__ float g_agg[N_NODES * D];      // mean-aggregated relu(x[src]) per node
__device__ int   g_deg[N_NODES];          // zeroed by scan_kernel after use (replay-safe)
__device__ int   g_woff[N_NODES];         // scan: exclusive prefix; after fill: rowptr[i+1]
__device__ int   g_src[N_EDGES];
__device__ float g_sum[D];                // zeroed by hist_kernel before gemm accumulates
__device__ float g_sumsq[D];

// ==================== helpers ====================
__device__ __forceinline__ uint32_t smem_to_u32(const void* p) {
    uint32_t a;
    asm("{ .reg .u64 t; cvta.to.shared.u64 t, %1; cvt.u32.u64 %0, t; }" : "=r"(a) : "l"(p));
    return a;
}
#define LDSM_X4(r0, r1, r2, r3, addr) \
    asm volatile("ldmatrix.sync.aligned.m8n8.x4.shared.b16 {%0,%1,%2,%3}, [%4];" \
        : "=r"(r0), "=r"(r1), "=r"(r2), "=r"(r3) : "r"(addr))
#define MMA_BF16(c, a, b0, b1) \
    asm volatile("mma.sync.aligned.m16n8k16.row.col.f32.bf16.bf16.f32 " \
        "{%0,%1,%2,%3}, {%4,%5,%6,%7}, {%8,%9}, {%0,%1,%2,%3};" \
        : "+f"((c)[0]), "+f"((c)[1]), "+f"((c)[2]), "+f"((c)[3]) \
        : "r"((a)[0]), "r"((a)[1]), "r"((a)[2]), "r"((a)[3]), "r"(b0), "r"(b1))

// ==================== kernel 1: histogram (+ zero BN accumulators) ====================
__global__ void hist_kernel(const int* __restrict__ ei) {
    const int i = blockIdx.x * blockDim.x + threadIdx.x;
    if (blockIdx.x == 0 && threadIdx.x < D) {   // re-arm BN accumulators for this call
        g_sum[threadIdx.x] = 0.f;
        g_sumsq[threadIdx.x] = 0.f;
    }
    if (i < N_EDGES / 4) {
        int4 d = reinterpret_cast<const int4*>(ei + N_EDGES)[i];
        atomicAdd(&g_deg[d.x], 1);
        atomicAdd(&g_deg[d.y], 1);
        atomicAdd(&g_deg[d.z], 1);
        atomicAdd(&g_deg[d.w], 1);
    }
}

// ==================== kernel 2: exclusive scan -> g_woff (and zero g_deg) ====================
#define SCAN_T 1024
#define CHUNK4 25                       // 1024 * 25 int4 = 25600 >= 25000
__global__ void scan_kernel() {
    __shared__ int spart[SCAN_T];
    const int t = threadIdx.x;
    const int n4 = N_NODES / 4;         // 25000
    const int lo = t * CHUNK4;
    const int hi = min(lo + CHUNK4, n4);
    int4* deg4  = reinterpret_cast<int4*>(g_deg);
    int4* woff4 = reinterpret_cast<int4*>(g_woff);
    int local = 0;
    for (int i = lo; i < hi; i++) {
        int4 d = deg4[i];
        local += d.x + d.y + d.z + d.w;
    }
    spart[t] = local;
    __syncthreads();
    for (int off = 1; off < SCAN_T; off <<= 1) {      // Hillis-Steele inclusive
        int v = (t >= off) ? spart[t - off] : 0;
        __syncthreads();
        spart[t] += v;
        __syncthreads();
    }
    int run = spart[t] - local;         // exclusive base for this chunk
    const int4 z4 = make_int4(0, 0, 0, 0);
    for (int i = lo; i < hi; i++) {
        int4 d = deg4[i];
        int4 w;
        w.x = run;
        w.y = run + d.x;
        w.z = w.y + d.y;
        w.w = w.z + d.z;
        woff4[i] = w;
        deg4[i] = z4;                   // zero for next call's hist
        run = w.w + d.w;
    }
}

// ==================== kernel 3: fill dst-sorted src lists ====================
__global__ void fill_kernel(const int* __restrict__ ei) {
    const int i = blockIdx.x * blockDim.x + threadIdx.x;
    if (i < N_EDGES / 4) {
        int4 s = reinterpret_cast<const int4*>(ei)[i];
        int4 d = reinterpret_cast<const int4*>(ei + N_EDGES)[i];
        g_src[atomicAdd(&g_woff[d.x], 1)] = s.x;
        g_src[atomicAdd(&g_woff[d.y], 1)] = s.y;
        g_src[atomicAdd(&g_woff[d.z], 1)] = s.z;
        g_src[atomicAdd(&g_woff[d.w], 1)] = s.w;
    }
}

// ==================== kernel 4: CSR mean aggregation (warp/node, shfl src bcast) ====
__global__ void agg_kernel(const float4* __restrict__ x4) {
    const int w    = (blockIdx.x * blockDim.x + threadIdx.x) >> 5;
    const int lane = threadIdx.x & 31;
    if (w >= N_NODES) return;
    const int start = (w == 0) ? 0 : g_woff[w - 1];   // post-fill: woff[i] = rowptr[i+1]
    const int end   = g_woff[w];
    float4 acc = make_float4(0.f, 0.f, 0.f, 0.f);
    for (int base = start; base < end; base += 32) {
        const int cnt = min(32, end - base);
        int sv = 0;
        if (lane < cnt) sv = g_src[base + lane];      // one coalesced load per chunk
        #pragma unroll 4
        for (int j = 0; j < cnt; j++) {
            int s = __shfl_sync(0xffffffffu, sv, j);
            float4 v = x4[s * 32 + lane];
            acc.x += fmaxf(v.x, 0.f); acc.y += fmaxf(v.y, 0.f);
            acc.z += fmaxf(v.z, 0.f); acc.w += fmaxf(v.w, 0.f);
        }
    }
    const float inv = 1.0f / (float)max(end - start, 1);
    acc.x *= inv; acc.y *= inv; acc.z *= inv; acc.w *= inv;
    reinterpret_cast<float4*>(g_agg)[w * 32 + lane] = acc;
}

// ==================== kernel 5: bf16 hi/lo mma.sync GEMM + fused BN stats ====================
// out = [g_agg | relu(x)] @ [Wl | Wr]^T  ; bias dropped (BN cancels it exactly)
#define SM_AHI 0
#define SM_ALO 32768
#define SM_WHI 65536
#define SM_WLO 131072
#define SM_RED 196608                    // float[2*D] block stats
#define SM_TOTAL (196608 + 2 * D * 4)    // 197632

__device__ __forceinline__ uint32_t aoff(int r, int c) {       // A: stride 256B, c in [0,16)
    return (uint32_t)(r * 256 + (((c & 8) | ((c ^ (r & 7)) & 7)) << 4));
}
__device__ __forceinline__ uint32_t woff_sw(int j, int c) {    // W: stride 512B, c in [0,32)
    return (uint32_t)(j * 512 + (((c & 24) | ((c ^ (j & 7)) & 7)) << 4));
}
__device__ __forceinline__ void split_row8(const float4& f0, const float4& f1,
                                           uint4& hi, uint4& lo) {
    __nv_bfloat162 h0 = __floats2bfloat162_rn(f0.x, f0.y);
    __nv_bfloat162 h1 = __floats2bfloat162_rn(f0.z, f0.w);
    __nv_bfloat162 h2 = __floats2bfloat162_rn(f1.x, f1.y);
    __nv_bfloat162 h3 = __floats2bfloat162_rn(f1.z, f1.w);
    float2 g0 = __bfloat1622float2(h0), g1 = __bfloat1622float2(h1);
    float2 g2 = __bfloat1622float2(h2), g3 = __bfloat1622float2(h3);
    __nv_bfloat162 l0 = __floats2bfloat162_rn(f0.x - g0.x, f0.y - g0.y);
    __nv_bfloat162 l1 = __floats2bfloat162_rn(f0.z - g1.x, f0.w - g1.y);
    __nv_bfloat162 l2 = __floats2bfloat162_rn(f1.x - g2.x, f1.y - g2.y);
    __nv_bfloat162 l3 = __floats2bfloat162_rn(f1.z - g3.x, f1.w - g3.y);
    hi = make_uint4(*(uint32_t*)&h0, *(uint32_t*)&h1, *(uint32_t*)&h2, *(uint32_t*)&h3);
    lo = make_uint4(*(uint32_t*)&l0, *(uint32_t*)&l1, *(uint32_t*)&l2, *(uint32_t*)&l3);
}

__global__ void __launch_bounds__(128, 1)
gemm_mma_kernel(const float* __restrict__ x,
                const float* __restrict__ Wl,
                const float* __restrict__ Wr,
                float* __restrict__ out) {
    extern __shared__ char smem[];
    const uint32_t sb = smem_to_u32(smem);
    float* red = reinterpret_cast<float*>(smem + SM_RED);
    const int tid  = threadIdx.x;
    const int lane = tid & 31;
    const int wid  = tid >> 5;

    for (int i = tid; i < 2 * D; i += 128) red[i] = 0.f;

    // ---- W conversion: row j = tid ----
    {
        const int j = tid;
        #pragma unroll 4
        for (int c = 0; c < 32; c++) {
            const float* src = (c < 16) ? &Wl[j * 128 + c * 8] : &Wr[j * 128 + (c - 16) * 8];
            float4 f0 = *reinterpret_cast<const float4*>(src);
            float4 f1 = *reinterpret_cast<const float4*>(src + 4);
            uint4 hi, lo;
            split_row8(f0, f1, hi, lo);
            uint32_t o = woff_sw(j, c);
            *reinterpret_cast<uint4*>(smem + SM_WHI + o) = hi;
            *reinterpret_cast<uint4*>(smem + SM_WLO + o) = lo;
        }
    }

    const int a_row  = wid * 32 + (lane & 15);
    const int a_csel = lane >> 4;
    const int b_jsub = (lane & 7) + ((lane >> 4) << 3);
    const int b_jx   = lane & 7;
    const int b_csel = (lane >> 3) & 1;

    float c[2][16][4];

    for (int t = blockIdx.x; t < NTILES; t += gridDim.x) {
        const int row0 = t * TM;
        #pragma unroll
        for (int mt = 0; mt < 2; mt++)
            #pragma unroll
            for (int nt = 0; nt < 16; nt++)
                #pragma unroll
                for (int q = 0; q < 4; q++) c[mt][nt][q] = 0.f;

        #pragma unroll 1
        for (int kh = 0; kh < 2; kh++) {
            __syncthreads();
            // ---- A prep: row r = tid ----
            {
                const int r = tid;
                const int n = row0 + r;
                const bool valid = (n < N_NODES);
                const float* srow = (kh == 0) ? &g_agg[(valid ? n : 0) * D]
                                              : &x[(valid ? n : 0) * D];
                #pragma unroll 4
                for (int cc = 0; cc < 16; cc++) {
                    float4 f0 = make_float4(0.f, 0.f, 0.f, 0.f), f1 = f0;
                    if (valid) {
                        f0 = *reinterpret_cast<const float4*>(srow + cc * 8);
                        f1 = *reinterpret_cast<const float4*>(srow + cc * 8 + 4);
                        if (kh == 1) {
                            f0.x = fmaxf(f0.x, 0.f); f0.y = fmaxf(f0.y, 0.f);
                            f0.z = fmaxf(f0.z, 0.f); f0.w = fmaxf(f0.w, 0.f);
                            f1.x = fmaxf(f1.x, 0.f); f1.y = fmaxf(f1.y, 0.f);
                            f1.z = fmaxf(f1.z, 0.f); f1.w = fmaxf(f1.w, 0.f);
                        }
                    }
                    uint4 hi, lo;
                    split_row8(f0, f1, hi, lo);
                    uint32_t o = aoff(r, cc);
                    *reinterpret_cast<uint4*>(smem + SM_AHI + o) = hi;
                    *reinterpret_cast<uint4*>(smem + SM_ALO + o) = lo;
                }
            }
            __syncthreads();

            // ---- compute: 3 passes x 8 k-steps over this K-half ----
            #pragma unroll 1
            for (int pass = 0; pass < 3; pass++) {
                const uint32_t Ab = sb + ((pass < 2) ? SM_AHI : SM_ALO);
                const uint32_t Wb = sb + ((pass == 1) ? SM_WLO : SM_WHI);
                #pragma unroll 1
                for (int ks = 0; ks < 8; ks++) {
                    const int kc = 2 * ks;
                    uint32_t a0[4], a1[4];
                    {
                        int cA = kc + a_csel;
                        LDSM_X4(a0[0], a0[1], a0[2], a0[3], Ab + aoff(a_row,      cA));
                        LDSM_X4(a1[0], a1[1], a1[2], a1[3], Ab + aoff(a_row + 16, cA));
                    }
                    const int cW = kh * 16 + kc + b_csel;
                    const uint32_t wsw = (uint32_t)((((cW & 24) | ((cW ^ b_jx) & 7)) << 4));
                    #pragma unroll
                    for (int np = 0; np < 8; np++) {
                        uint32_t b[4];
                        uint32_t baddr = Wb + (uint32_t)((np * 16 + b_jsub) * 512) + wsw;
                        LDSM_X4(b[0], b[1], b[2], b[3], baddr);
                        MMA_BF16(c[0][2 * np],     a0, b[0], b[1]);
                        MMA_BF16(c[0][2 * np + 1], a0, b[2], b[3]);
                        MMA_BF16(c[1][2 * np],     a1, b[0], b[1]);
                        MMA_BF16(c[1][2 * np + 1], a1, b[2], b[3]);
                    }
                }
            }
        }

        // ---- epilogue: stores + fused BN stats (butterfly column reduce) ----
        const int qrow = lane >> 2;
        const int qcol = (lane & 3) * 2;
        #pragma unroll
        for (int mt = 0; mt < 2; mt++) {
            const int r_lo = row0 + wid * 32 + mt * 16 + qrow;
            #pragma unroll
            for (int nt = 0; nt < 16; nt++) {
                const int col = nt * 8 + qcol;
                if (r_lo < N_NODES)
                    *reinterpret_cast<float2*>(&out[r_lo * D + col]) =
                        make_float2(c[mt][nt][0], c[mt][nt][1]);
                if (r_lo + 8 < N_NODES)
                    *reinterpret_cast<float2*>(&out[(r_lo + 8) * D + col]) =
                        make_float2(c[mt][nt][2], c[mt][nt][3]);
            }
        }
        #pragma unroll
        for (int nt = 0; nt < 16; nt++) {
            // invalid (padded) rows have c == 0, so they contribute nothing
            float s0 = c[0][nt][0] + c[0][nt][2] + c[1][nt][0] + c[1][nt][2];
            float s1 = c[0][nt][1] + c[0][nt][3] + c[1][nt][1] + c[1][nt][3];
            float z0 = c[0][nt][0] * c[0][nt][0] + c[0][nt][2] * c[0][nt][2]
                     + c[1][nt][0] * c[1][nt][0] + c[1][nt][2] * c[1][nt][2];
            float z1 = c[0][nt][1] * c[0][nt][1] + c[0][nt][3] * c[0][nt][3]
                     + c[1][nt][1] * c[1][nt][1] + c[1][nt][3] * c[1][nt][3];
            #pragma unroll
            for (int mask = 4; mask <= 16; mask <<= 1) {
                s0 += __shfl_xor_sync(0xffffffffu, s0, mask);
                s1 += __shfl_xor_sync(0xffffffffu, s1, mask);
                z0 += __shfl_xor_sync(0xffffffffu, z0, mask);
                z1 += __shfl_xor_sync(0xffffffffu, z1, mask);
            }
            if (lane < 4) {                      // lanes 0..3 hold distinct column pairs
                const int col = nt * 8 + lane * 2;
                atomicAdd(&red[col], s0);
                atomicAdd(&red[col + 1], s1);
                atomicAdd(&red[D + col], z0);
                atomicAdd(&red[D + col + 1], z1);
            }
        }
    }

    __syncthreads();
    if (tid < D) {
        atomicAdd(&g_sum[tid], red[tid]);
        atomicAdd(&g_sumsq[tid], red[D + tid]);
    }
}

// ==================== kernel 6: batchnorm normalize ====================
__global__ void bn_kernel(const float* __restrict__ gamma,
                          const float* __restrict__ beta,
                          float* __restrict__ out) {
    __shared__ float sscale[D];
    __shared__ float sshift[D];
    int tid = threadIdx.x;
    if (tid < D) {
        float mu  = g_sum[tid] * (1.0f / N_NODES);
        float var = g_sumsq[tid] * (1.0f / N_NODES) - mu * mu;
        float sc  = gamma[tid] * rsqrtf(var + BN_EPS);
        sscale[tid] = sc;
        sshift[tid] = beta[tid] - mu * sc;
    }
    __syncthreads();
    const int total = N_NODES * (D / 4);
    float4* o4 = reinterpret_cast<float4*>(out);
    for (int i = blockIdx.x * blockDim.x + tid; i < total; i += gridDim.x * blockDim.x) {
        int c4 = i & 31;
        float4 v  = o4[i];
        float4 sc = *reinterpret_cast<const float4*>(&sscale[c4 * 4]);
        float4 sh = *reinterpret_cast<const float4*>(&sshift[c4 * 4]);
        v.x = v.x * sc.x + sh.x; v.y = v.y * sc.y + sh.y;
        v.z = v.z * sc.z + sh.z; v.w = v.w * sc.w + sh.w;
        o4[i] = v;
    }
}

// ==================== launch ====================
extern "C" void kernel_launch(void* const* d_in, const int* in_sizes, int n_in,
                              void* d_out, int out_size) {
    const float* x     = (const float*)d_in[0];
    const float* Wl    = (const float*)d_in[2];
    const float* Wr    = (const float*)d_in[4];
    const float* gamma = (const float*)d_in[5];
    const float* beta  = (const float*)d_in[6];
    const int*   ei    = (const int*)d_in[7];
    float* out = (float*)d_out;

    static bool attr_done = false;
    if (!attr_done) {
        cudaFuncSetAttribute(gemm_mma_kernel,
                             cudaFuncAttributeMaxDynamicSharedMemorySize, SM_TOTAL);
        attr_done = true;
    }

    hist_kernel<<<(N_EDGES / 4 + 255) / 256, 256>>>(ei);          // idx 0
    scan_kernel<<<1, SCAN_T>>>();                                 // idx 1
    fill_kernel<<<(N_EDGES / 4 + 255) / 256, 256>>>(ei);          // idx 2
    agg_kernel<<<(N_NODES * 32 + 255) / 256, 256>>>((const float4*)x);  // idx 3 -> profiled
    gemm_mma_kernel<<<148, 128, SM_TOTAL>>>(x, Wl, Wr, out);      // idx 4
    bn_kernel<<<2048, 256>>>(gamma, beta, out);                   // idx 5
}